// round 1
// baseline (speedup 1.0000x reference)
#include <cuda_runtime.h>

// Problem dims
#define NCC 4
#define BSZ 16
#define HH  64
#define WW  64
#define OCC 12
#define NTT 32
#define SSLICE (BSZ*HH*WW*OCC)   // 786432 floats per (BS,H,W,OC) slab

// Persistent device state (allocation-free scratch)
__device__ float g_class_h[NCC*SSLICE];
__device__ float g_class_c[NCC*SSLICE];
__device__ float g_genh[2][SSLICE];   // double-buffered recurrent h
__device__ float g_genc[SSLICE];
__device__ float g_hnew[SSLICE];

__device__ __forceinline__ float hsig(float x) {
    // jax.nn.hard_sigmoid = relu6(x+3)/6
    return fminf(fmaxf(x + 3.0f, 0.0f), 6.0f) * (1.0f/6.0f);
}

// --------------------------------------------------------------------------
// Zero-init all recurrent state + output accumulator (runs once per replay)
// --------------------------------------------------------------------------
__global__ void zero_kernel(float* __restrict__ out)
{
    const int tid    = blockIdx.x * blockDim.x + threadIdx.x;
    const int stride = gridDim.x * blockDim.x;
    for (int i = tid; i < NCC*SSLICE; i += stride) {
        g_class_h[i] = 0.0f;
        g_class_c[i] = 0.0f;
    }
    for (int i = tid; i < SSLICE; i += stride) {
        g_genh[0][i] = 0.0f;
        g_genc[i]    = 0.0f;
        out[i]       = 0.0f;
    }
}

// --------------------------------------------------------------------------
// General ConvLSTM cell.
// Input channels: 60 = 48 (class_h raw-reshaped to (BS,H,W,48)) + 12 (gen_h).
// Output: 48 gate channels -> gen_h (parity-swapped buffer), gen_c in place.
// grid (8,16) = (row-tiles, batch). block 256 = 64 cols x 4 oc-groups.
// Each thread: 8 rows x 12 oc accumulators.
// --------------------------------------------------------------------------
#define A_ICT 60
#define A_CH  20
#define A_NCH 3
#define A_CHP 21
#define A_SW  (9*A_ICT*48)          // 25920 floats
#define A_SIN (660*A_CHP)           // 13860 floats (10 rows x 66 cols x CHP)
#define A_SZ  (4*64*12)             // 3072 floats gate-exchange buffer
#define A_SMEM_BYTES ((A_SW + A_SIN + A_SZ)*4)

__global__ __launch_bounds__(256, 1)
void gen_cell_kernel(const float* __restrict__ Wx, const float* __restrict__ Wh,
                     const float* __restrict__ bias, int par)
{
    extern __shared__ float smem[];
    float* sW  = smem;                 // [9][60][48]
    float* sIn = smem + A_SW;          // [10][66][A_CHP]
    float* sZ  = smem + A_SW + A_SIN;  // [4][64][12]

    const int tid = threadIdx.x;
    const int tx  = tid & 63;
    const int og  = tid >> 6;          // 0..3, owns oc = og*12 .. og*12+11
    const int b   = blockIdx.y;
    const int y0  = blockIdx.x * 8;

    const float* genh_in  = g_genh[par];
    float*       genh_out = g_genh[par ^ 1];

    // Stage combined weights [k][ic][oc]: ic<48 -> Wx_g, else Wh_g
    for (int e = tid; e < A_SW; e += 256) {
        int oc = e % 48;
        int r  = e / 48;
        int ic = r % A_ICT;
        int k  = r / A_ICT;
        sW[e] = (ic < 48) ? Wx[(k*48 + ic)*48 + oc]
                          : Wh[(k*12 + (ic - 48))*48 + oc];
    }

    float acc[8][12];
    #pragma unroll
    for (int r = 0; r < 8; ++r)
        #pragma unroll
        for (int j = 0; j < 12; ++j) acc[r][j] = 0.0f;

    #pragma unroll 1
    for (int ch = 0; ch < A_NCH; ++ch) {
        __syncthreads();
        // Stage input tile (rows y0-1..y0+8, cols -1..64) for this ic-chunk
        for (int e = tid; e < 660*A_CH; e += 256) {
            int px  = e / A_CH;
            int icc = e - px*A_CH;
            int yy  = px / 66;
            int xx  = px - yy*66;
            int gy  = y0 + yy - 1;
            int gx  = xx - 1;
            int ic  = ch*A_CH + icc;
            float v = 0.0f;
            if ((unsigned)gy < 64u && (unsigned)gx < 64u) {
                int pidx = (b*64 + gy)*64 + gx;
                v = (ic < 48) ? g_class_h[pidx*48 + ic]          // raw reshape view
                              : genh_in[pidx*12 + (ic - 48)];
            }
            sIn[px*A_CHP + icc] = v;
        }
        __syncthreads();

        #pragma unroll 1
        for (int k = 0; k < 9; ++k) {
            const int ky = k / 3;
            const int kx = k - ky*3;
            const float* wrow = sW + (k*A_ICT + ch*A_CH)*48 + og*12;
            const float* xrow = sIn + (ky*66 + tx + kx)*A_CHP;
            #pragma unroll 1
            for (int icc = 0; icc < A_CH; ++icc) {
                const float4 w0 = *(const float4*)(wrow + icc*48);
                const float4 w1 = *(const float4*)(wrow + icc*48 + 4);
                const float4 w2 = *(const float4*)(wrow + icc*48 + 8);
                #pragma unroll
                for (int r = 0; r < 8; ++r) {
                    const float v = xrow[r*(66*A_CHP) + icc];
                    acc[r][0]  = fmaf(v, w0.x, acc[r][0]);
                    acc[r][1]  = fmaf(v, w0.y, acc[r][1]);
                    acc[r][2]  = fmaf(v, w0.z, acc[r][2]);
                    acc[r][3]  = fmaf(v, w0.w, acc[r][3]);
                    acc[r][4]  = fmaf(v, w1.x, acc[r][4]);
                    acc[r][5]  = fmaf(v, w1.y, acc[r][5]);
                    acc[r][6]  = fmaf(v, w1.z, acc[r][6]);
                    acc[r][7]  = fmaf(v, w1.w, acc[r][7]);
                    acc[r][8]  = fmaf(v, w2.x, acc[r][8]);
                    acc[r][9]  = fmaf(v, w2.y, acc[r][9]);
                    acc[r][10] = fmaf(v, w2.z, acc[r][10]);
                    acc[r][11] = fmaf(v, w2.w, acc[r][11]);
                }
            }
        }
    }

    // Epilogue: exchange gates (i,f,g,o live in different og threads), apply LSTM
    #pragma unroll 1
    for (int r = 0; r < 8; ++r) {
        __syncthreads();
        #pragma unroll
        for (int j = 0; j < 12; ++j)
            sZ[(og*64 + tx)*12 + j] = acc[r][j];
        __syncthreads();
        #pragma unroll 1
        for (int it = tid; it < 768; it += 256) {
            int px = it / 12;
            int j  = it - px*12;
            float zi = sZ[(0*64 + px)*12 + j] + bias[j];
            float zf = sZ[(1*64 + px)*12 + j] + bias[12 + j];
            float zg = sZ[(2*64 + px)*12 + j] + bias[24 + j];
            float zo = sZ[(3*64 + px)*12 + j] + bias[36 + j];
            float fi = hsig(zi), ff = hsig(zf), fo = hsig(zo);
            int gy  = y0 + r;
            int idx = ((b*64 + gy)*64 + px)*12 + j;
            float cn = ff * g_genc[idx] + fi * tanhf(zg);
            g_genc[idx]   = cn;
            genh_out[idx] = fo * tanhf(cn);
        }
    }
}

// --------------------------------------------------------------------------
// Class ConvLSTM cell.
// Input channels: 36 = 12 (frame_t) + 12 (fresh gen_h) + 12 (class_h[cid]).
// Writes h_new into g_hnew (scatter deferred), class_c[cid] in place.
// --------------------------------------------------------------------------
#define B_ICT 36
#define B_CH  18
#define B_NCH 2
#define B_CHP 19
#define B_SW  (9*B_ICT*48)          // 15552 floats
#define B_SIN (660*B_CHP)           // 12540 floats
#define B_SMEM_BYTES ((B_SW + B_SIN + A_SZ)*4)

__global__ __launch_bounds__(256, 1)
void cls_cell_kernel(const float* __restrict__ x, const int* __restrict__ class_ids,
                     const float* __restrict__ Wx, const float* __restrict__ Wh,
                     const float* __restrict__ bias, int t, int par)
{
    extern __shared__ float smem[];
    float* sW  = smem;
    float* sIn = smem + B_SW;
    float* sZ  = smem + B_SW + B_SIN;

    const int tid = threadIdx.x;
    const int tx  = tid & 63;
    const int og  = tid >> 6;
    const int b   = blockIdx.y;
    const int y0  = blockIdx.x * 8;
    const int cid = __ldg(class_ids + t);

    const float* genh_new = g_genh[par ^ 1];
    const float* chh      = g_class_h + (size_t)cid * SSLICE;

    for (int e = tid; e < B_SW; e += 256) {
        int oc = e % 48;
        int r  = e / 48;
        int ic = r % B_ICT;
        int k  = r / B_ICT;
        sW[e] = (ic < 24) ? Wx[(k*24 + ic)*48 + oc]
                          : Wh[(k*12 + (ic - 24))*48 + oc];
    }

    float acc[8][12];
    #pragma unroll
    for (int r = 0; r < 8; ++r)
        #pragma unroll
        for (int j = 0; j < 12; ++j) acc[r][j] = 0.0f;

    #pragma unroll 1
    for (int ch = 0; ch < B_NCH; ++ch) {
        __syncthreads();
        for (int e = tid; e < 660*B_CH; e += 256) {
            int px  = e / B_CH;
            int icc = e - px*B_CH;
            int yy  = px / 66;
            int xx  = px - yy*66;
            int gy  = y0 + yy - 1;
            int gx  = xx - 1;
            int ic  = ch*B_CH + icc;
            float v = 0.0f;
            if ((unsigned)gy < 64u && (unsigned)gx < 64u) {
                int pidx = (b*64 + gy)*64 + gx;
                if (ic < 12)       v = x[(( (size_t)(b*NTT + t)*64 + gy)*64 + gx)*12 + ic];
                else if (ic < 24)  v = genh_new[pidx*12 + (ic - 12)];
                else               v = chh[pidx*12 + (ic - 24)];
            }
            sIn[px*B_CHP + icc] = v;
        }
        __syncthreads();

        #pragma unroll 1
        for (int k = 0; k < 9; ++k) {
            const int ky = k / 3;
            const int kx = k - ky*3;
            const float* wrow = sW + (k*B_ICT + ch*B_CH)*48 + og*12;
            const float* xrow = sIn + (ky*66 + tx + kx)*B_CHP;
            #pragma unroll 1
            for (int icc = 0; icc < B_CH; ++icc) {
                const float4 w0 = *(const float4*)(wrow + icc*48);
                const float4 w1 = *(const float4*)(wrow + icc*48 + 4);
                const float4 w2 = *(const float4*)(wrow + icc*48 + 8);
                #pragma unroll
                for (int r = 0; r < 8; ++r) {
                    const float v = xrow[r*(66*B_CHP) + icc];
                    acc[r][0]  = fmaf(v, w0.x, acc[r][0]);
                    acc[r][1]  = fmaf(v, w0.y, acc[r][1]);
                    acc[r][2]  = fmaf(v, w0.z, acc[r][2]);
                    acc[r][3]  = fmaf(v, w0.w, acc[r][3]);
                    acc[r][4]  = fmaf(v, w1.x, acc[r][4]);
                    acc[r][5]  = fmaf(v, w1.y, acc[r][5]);
                    acc[r][6]  = fmaf(v, w1.z, acc[r][6]);
                    acc[r][7]  = fmaf(v, w1.w, acc[r][7]);
                    acc[r][8]  = fmaf(v, w2.x, acc[r][8]);
                    acc[r][9]  = fmaf(v, w2.y, acc[r][9]);
                    acc[r][10] = fmaf(v, w2.z, acc[r][10]);
                    acc[r][11] = fmaf(v, w2.w, acc[r][11]);
                }
            }
        }
    }

    float* chc = g_class_c + (size_t)cid * SSLICE;

    #pragma unroll 1
    for (int r = 0; r < 8; ++r) {
        __syncthreads();
        #pragma unroll
        for (int j = 0; j < 12; ++j)
            sZ[(og*64 + tx)*12 + j] = acc[r][j];
        __syncthreads();
        #pragma unroll 1
        for (int it = tid; it < 768; it += 256) {
            int px = it / 12;
            int j  = it - px*12;
            float zi = sZ[(0*64 + px)*12 + j] + bias[j];
            float zf = sZ[(1*64 + px)*12 + j] + bias[12 + j];
            float zg = sZ[(2*64 + px)*12 + j] + bias[24 + j];
            float zo = sZ[(3*64 + px)*12 + j] + bias[36 + j];
            float fi = hsig(zi), ff = hsig(zf), fo = hsig(zo);
            int gy  = y0 + r;
            int idx = ((b*64 + gy)*64 + px)*12 + j;
            float cn = ff * chc[idx] + fi * tanhf(zg);
            chc[idx]    = cn;
            g_hnew[idx] = fo * tanhf(cn);
        }
    }
}

// --------------------------------------------------------------------------
// Scatter h_new into class_h[cid] and accumulate into the output sum.
// Separate kernel so the class-cell conv never races its own bank update.
// --------------------------------------------------------------------------
__global__ void scatter_kernel(const int* __restrict__ class_ids, int t,
                               float* __restrict__ out)
{
    const int cid = __ldg(class_ids + t);
    const int i = blockIdx.x * blockDim.x + threadIdx.x;
    if (i < SSLICE/4) {
        float4 h = reinterpret_cast<const float4*>(g_hnew)[i];
        reinterpret_cast<float4*>(g_class_h + (size_t)cid*SSLICE)[i] = h;
        float4 o = reinterpret_cast<float4*>(out)[i];
        o.x += h.x; o.y += h.y; o.z += h.z; o.w += h.w;
        reinterpret_cast<float4*>(out)[i] = o;
    }
}

// --------------------------------------------------------------------------
extern "C" void kernel_launch(void* const* d_in, const int* in_sizes, int n_in,
                              void* d_out, int out_size)
{
    const float* x    = (const float*)d_in[0];
    const int*   cids = (const int*)d_in[1];
    const float* Wxg  = (const float*)d_in[2];
    const float* Whg  = (const float*)d_in[3];
    const float* bg   = (const float*)d_in[4];
    const float* Wxc  = (const float*)d_in[5];
    const float* Whc  = (const float*)d_in[6];
    const float* bc   = (const float*)d_in[7];
    float* out = (float*)d_out;

    cudaFuncSetAttribute(gen_cell_kernel, cudaFuncAttributeMaxDynamicSharedMemorySize, A_SMEM_BYTES);
    cudaFuncSetAttribute(cls_cell_kernel, cudaFuncAttributeMaxDynamicSharedMemorySize, B_SMEM_BYTES);

    zero_kernel<<<1024, 256>>>(out);

    for (int t = 0; t < NTT; ++t) {
        const int par = t & 1;
        gen_cell_kernel<<<dim3(8, 16), 256, A_SMEM_BYTES>>>(Wxg, Whg, bg, par);
        cls_cell_kernel<<<dim3(8, 16), 256, B_SMEM_BYTES>>>(x, cids, Wxc, Whc, bc, t, par);
        scatter_kernel<<<(SSLICE/4 + 255)/256, 256>>>(cids, t, out);
    }
}

// round 2
// speedup vs baseline: 1.0266x; 1.0266x over previous
#include <cuda_runtime.h>

// Problem dims
#define NCC 4
#define BSZ 16
#define HH  64
#define WW  64
#define OCC 12
#define NTT 32
#define SSLICE (BSZ*HH*WW*OCC)   // 786432 floats per (BS,H,W,OC) slab

// Persistent device state (allocation-free scratch)
__device__ float g_class_h[NCC*SSLICE];
__device__ float g_class_c[NCC*SSLICE];
__device__ float g_genh[2][SSLICE];   // double-buffered recurrent h
__device__ float g_genc[SSLICE];
__device__ float g_hnew[SSLICE];

__device__ __forceinline__ float hsig(float x) {
    return fminf(fmaxf(x + 3.0f, 0.0f), 6.0f) * (1.0f/6.0f);
}

// Packed f32x2 helpers (Blackwell double-rate fp32)
__device__ __forceinline__ unsigned long long pack2(float x) {
    unsigned long long r;
    unsigned int xi = __float_as_uint(x);
    asm("mov.b64 %0, {%1, %1};" : "=l"(r) : "r"(xi));
    return r;
}
__device__ __forceinline__ void ffma2(unsigned long long& d,
                                      unsigned long long a,
                                      unsigned long long b) {
    asm("fma.rn.f32x2 %0, %1, %2, %0;" : "+l"(d) : "l"(a), "l"(b));
}
__device__ __forceinline__ float2 unpack2(unsigned long long v) {
    float2 r;
    asm("mov.b64 {%0, %1}, %2;" : "=f"(r.x), "=f"(r.y) : "l"(v));
    return r;
}

// --------------------------------------------------------------------------
__global__ void zero_kernel(float* __restrict__ out)
{
    const int tid    = blockIdx.x * blockDim.x + threadIdx.x;
    const int stride = gridDim.x * blockDim.x;
    for (int i = tid; i < NCC*SSLICE; i += stride) {
        g_class_h[i] = 0.0f;
        g_class_c[i] = 0.0f;
    }
    for (int i = tid; i < SSLICE; i += stride) {
        g_genh[0][i] = 0.0f;
        g_genc[i]    = 0.0f;
        out[i]       = 0.0f;
    }
}

// --------------------------------------------------------------------------
// General ConvLSTM cell. 60 input ch (48 class-bank reshape + 12 gen_h),
// 48 gate ch out. grid (8,16)=(row-tiles,batch). block 256 = 64 cols x 4
// row-groups; each thread owns 2 rows x 48 oc (all 4 gates of 12 channels)
// as 24 packed f32x2 accumulators per row -> fully local LSTM epilogue.
// --------------------------------------------------------------------------
#define A_ICT 60
#define A_CH  20
#define A_NCH 3
#define A_CHP 21
#define A_SW  (9*A_ICT*48)          // 25920 floats
#define A_SIN (660*A_CHP)           // 13860 floats (10 rows x 66 cols x CHP)
#define A_SMEM_BYTES ((A_SW + A_SIN)*4)

__global__ __launch_bounds__(256, 1)
void gen_cell_kernel(const float* __restrict__ Wx, const float* __restrict__ Wh,
                     const float* __restrict__ bias, int par)
{
    extern __shared__ float smem[];
    float* sW  = smem;                 // [9][60][48]
    float* sIn = smem + A_SW;          // [10][66][A_CHP]

    const int tid = threadIdx.x;
    const int tx  = tid & 63;
    const int rg  = tid >> 6;          // 0..3, owns rows y0+rg*2, +1
    const int b   = blockIdx.y;
    const int y0  = blockIdx.x * 8;

    const float* genh_in  = g_genh[par];
    float*       genh_out = g_genh[par ^ 1];

    // Stage combined weights [k][ic][oc]
    for (int e = tid; e < A_SW; e += 256) {
        int oc = e % 48;
        int r  = e / 48;
        int ic = r % A_ICT;
        int k  = r / A_ICT;
        sW[e] = (ic < 48) ? Wx[(k*48 + ic)*48 + oc]
                          : Wh[(k*12 + (ic - 48))*48 + oc];
    }

    unsigned long long acc[2][24];
    #pragma unroll
    for (int r = 0; r < 2; ++r)
        #pragma unroll
        for (int p = 0; p < 24; ++p) acc[r][p] = 0ull;

    #pragma unroll 1
    for (int ch = 0; ch < A_NCH; ++ch) {
        __syncthreads();
        for (int e = tid; e < 660*A_CH; e += 256) {
            int px  = e / A_CH;
            int icc = e - px*A_CH;
            int yy  = px / 66;
            int xx  = px - yy*66;
            int gy  = y0 + yy - 1;
            int gx  = xx - 1;
            int ic  = ch*A_CH + icc;
            float v = 0.0f;
            if ((unsigned)gy < 64u && (unsigned)gx < 64u) {
                int pidx = (b*64 + gy)*64 + gx;
                v = (ic < 48) ? g_class_h[pidx*48 + ic]
                              : genh_in[pidx*12 + (ic - 48)];
            }
            sIn[px*A_CHP + icc] = v;
        }
        __syncthreads();

        #pragma unroll 1
        for (int k = 0; k < 9; ++k) {
            const int ky = k / 3;
            const int kx = k - ky*3;
            const float* wbase = sW + (k*A_ICT + ch*A_CH)*48;
            const float* x0 = sIn + ((rg*2 + ky)*66 + tx + kx)*A_CHP;
            #pragma unroll 1
            for (int icc = 0; icc < A_CH; ++icc) {
                unsigned long long xp0 = pack2(x0[icc]);
                unsigned long long xp1 = pack2(x0[66*A_CHP + icc]);
                const unsigned long long* wp =
                    (const unsigned long long*)(wbase + icc*48);
                #pragma unroll
                for (int p = 0; p < 24; ++p) {
                    unsigned long long w = wp[p];
                    ffma2(acc[0][p], xp0, w);
                    ffma2(acc[1][p], xp1, w);
                }
            }
        }
    }

    // Local LSTM epilogue (no gate exchange needed)
    #pragma unroll
    for (int r = 0; r < 2; ++r) {
        float z[48];
        #pragma unroll
        for (int p = 0; p < 24; ++p) {
            float2 v = unpack2(acc[r][p]);
            z[2*p] = v.x; z[2*p+1] = v.y;
        }
        const int gy = y0 + rg*2 + r;
        #pragma unroll
        for (int j = 0; j < 12; ++j) {
            float zi = z[j]      + __ldg(bias + j);
            float zf = z[12 + j] + __ldg(bias + 12 + j);
            float zg = z[24 + j] + __ldg(bias + 24 + j);
            float zo = z[36 + j] + __ldg(bias + 36 + j);
            float fi = hsig(zi), ff = hsig(zf), fo = hsig(zo);
            int idx = ((b*64 + gy)*64 + tx)*12 + j;
            float cn = ff * g_genc[idx] + fi * tanhf(zg);
            g_genc[idx]   = cn;
            genh_out[idx] = fo * tanhf(cn);
        }
    }
}

// --------------------------------------------------------------------------
// Class ConvLSTM cell. 36 input ch (12 frame + 12 fresh gen_h + 12 class_h[cid]).
// --------------------------------------------------------------------------
#define B_ICT 36
#define B_CH  18
#define B_NCH 2
#define B_CHP 19
#define B_SW  (9*B_ICT*48)          // 15552 floats
#define B_SIN (660*B_CHP)           // 12540 floats
#define B_SMEM_BYTES ((B_SW + B_SIN)*4)

__global__ __launch_bounds__(256, 1)
void cls_cell_kernel(const float* __restrict__ x, const int* __restrict__ class_ids,
                     const float* __restrict__ Wx, const float* __restrict__ Wh,
                     const float* __restrict__ bias, int t, int par)
{
    extern __shared__ float smem[];
    float* sW  = smem;
    float* sIn = smem + B_SW;

    const int tid = threadIdx.x;
    const int tx  = tid & 63;
    const int rg  = tid >> 6;
    const int b   = blockIdx.y;
    const int y0  = blockIdx.x * 8;
    const int cid = __ldg(class_ids + t);

    const float* genh_new = g_genh[par ^ 1];
    const float* chh      = g_class_h + (size_t)cid * SSLICE;

    for (int e = tid; e < B_SW; e += 256) {
        int oc = e % 48;
        int r  = e / 48;
        int ic = r % B_ICT;
        int k  = r / B_ICT;
        sW[e] = (ic < 24) ? Wx[(k*24 + ic)*48 + oc]
                          : Wh[(k*12 + (ic - 24))*48 + oc];
    }

    unsigned long long acc[2][24];
    #pragma unroll
    for (int r = 0; r < 2; ++r)
        #pragma unroll
        for (int p = 0; p < 24; ++p) acc[r][p] = 0ull;

    #pragma unroll 1
    for (int ch = 0; ch < B_NCH; ++ch) {
        __syncthreads();
        for (int e = tid; e < 660*B_CH; e += 256) {
            int px  = e / B_CH;
            int icc = e - px*B_CH;
            int yy  = px / 66;
            int xx  = px - yy*66;
            int gy  = y0 + yy - 1;
            int gx  = xx - 1;
            int ic  = ch*B_CH + icc;
            float v = 0.0f;
            if ((unsigned)gy < 64u && (unsigned)gx < 64u) {
                int pidx = (b*64 + gy)*64 + gx;
                if (ic < 12)       v = x[(((size_t)(b*NTT + t)*64 + gy)*64 + gx)*12 + ic];
                else if (ic < 24)  v = genh_new[pidx*12 + (ic - 12)];
                else               v = chh[pidx*12 + (ic - 24)];
            }
            sIn[px*B_CHP + icc] = v;
        }
        __syncthreads();

        #pragma unroll 1
        for (int k = 0; k < 9; ++k) {
            const int ky = k / 3;
            const int kx = k - ky*3;
            const float* wbase = sW + (k*B_ICT + ch*B_CH)*48;
            const float* x0 = sIn + ((rg*2 + ky)*66 + tx + kx)*B_CHP;
            #pragma unroll 1
            for (int icc = 0; icc < B_CH; ++icc) {
                unsigned long long xp0 = pack2(x0[icc]);
                unsigned long long xp1 = pack2(x0[66*B_CHP + icc]);
                const unsigned long long* wp =
                    (const unsigned long long*)(wbase + icc*48);
                #pragma unroll
                for (int p = 0; p < 24; ++p) {
                    unsigned long long w = wp[p];
                    ffma2(acc[0][p], xp0, w);
                    ffma2(acc[1][p], xp1, w);
                }
            }
        }
    }

    float* chc = g_class_c + (size_t)cid * SSLICE;

    #pragma unroll
    for (int r = 0; r < 2; ++r) {
        float z[48];
        #pragma unroll
        for (int p = 0; p < 24; ++p) {
            float2 v = unpack2(acc[r][p]);
            z[2*p] = v.x; z[2*p+1] = v.y;
        }
        const int gy = y0 + rg*2 + r;
        #pragma unroll
        for (int j = 0; j < 12; ++j) {
            float zi = z[j]      + __ldg(bias + j);
            float zf = z[12 + j] + __ldg(bias + 12 + j);
            float zg = z[24 + j] + __ldg(bias + 24 + j);
            float zo = z[36 + j] + __ldg(bias + 36 + j);
            float fi = hsig(zi), ff = hsig(zf), fo = hsig(zo);
            int idx = ((b*64 + gy)*64 + tx)*12 + j;
            float cn = ff * chc[idx] + fi * tanhf(zg);
            chc[idx]    = cn;
            g_hnew[idx] = fo * tanhf(cn);
        }
    }
}

// --------------------------------------------------------------------------
__global__ void scatter_kernel(const int* __restrict__ class_ids, int t,
                               float* __restrict__ out)
{
    const int cid = __ldg(class_ids + t);
    const int i = blockIdx.x * blockDim.x + threadIdx.x;
    if (i < SSLICE/4) {
        float4 h = reinterpret_cast<const float4*>(g_hnew)[i];
        reinterpret_cast<float4*>(g_class_h + (size_t)cid*SSLICE)[i] = h;
        float4 o = reinterpret_cast<float4*>(out)[i];
        o.x += h.x; o.y += h.y; o.z += h.z; o.w += h.w;
        reinterpret_cast<float4*>(out)[i] = o;
    }
}

// --------------------------------------------------------------------------
extern "C" void kernel_launch(void* const* d_in, const int* in_sizes, int n_in,
                              void* d_out, int out_size)
{
    const float* x    = (const float*)d_in[0];
    const int*   cids = (const int*)d_in[1];
    const float* Wxg  = (const float*)d_in[2];
    const float* Whg  = (const float*)d_in[3];
    const float* bg   = (const float*)d_in[4];
    const float* Wxc  = (const float*)d_in[5];
    const float* Whc  = (const float*)d_in[6];
    const float* bc   = (const float*)d_in[7];
    float* out = (float*)d_out;

    cudaFuncSetAttribute(gen_cell_kernel, cudaFuncAttributeMaxDynamicSharedMemorySize, A_SMEM_BYTES);
    cudaFuncSetAttribute(cls_cell_kernel, cudaFuncAttributeMaxDynamicSharedMemorySize, B_SMEM_BYTES);

    zero_kernel<<<1024, 256>>>(out);

    for (int t = 0; t < NTT; ++t) {
        const int par = t & 1;
        gen_cell_kernel<<<dim3(8, 16), 256, A_SMEM_BYTES>>>(Wxg, Whg, bg, par);
        cls_cell_kernel<<<dim3(8, 16), 256, B_SMEM_BYTES>>>(x, cids, Wxc, Whc, bc, t, par);
        scatter_kernel<<<(SSLICE/4 + 255)/256, 256>>>(cids, t, out);
    }
}

// round 4
// speedup vs baseline: 1.2818x; 1.2486x over previous
#include <cuda_runtime.h>

// Problem dims
#define NCC 4
#define BSZ 16
#define HH  64
#define WW  64
#define OCC 12
#define NTT 32
#define SSLICE (BSZ*HH*WW*OCC)   // 786432 floats per (BS,H,W,OC) slab

// Persistent device state (16B-aligned for float4 access)
__device__ __align__(16) float g_class_h[NCC*SSLICE];
__device__ __align__(16) float g_class_c[NCC*SSLICE];
__device__ __align__(16) float g_genh[2][SSLICE];
__device__ __align__(16) float g_genc[SSLICE];
__device__ __align__(16) float g_hnew[SSLICE];

__device__ __forceinline__ float hsig(float x) {
    return fminf(fmaxf(x + 3.0f, 0.0f), 6.0f) * (1.0f/6.0f);
}

typedef unsigned long long ull;

__device__ __forceinline__ ull pack2(float x) {
    ull r;
    unsigned int xi = __float_as_uint(x);
    asm("mov.b64 %0, {%1, %1};" : "=l"(r) : "r"(xi));
    return r;
}
__device__ __forceinline__ void ffma2(ull& d, ull a, ull b) {
    asm("fma.rn.f32x2 %0, %1, %2, %0;" : "+l"(d) : "l"(a), "l"(b));
}
__device__ __forceinline__ float2 unpack2(ull v) {
    float2 r;
    asm("mov.b64 {%0, %1}, %2;" : "=f"(r.x), "=f"(r.y) : "l"(v));
    return r;
}

// --------------------------------------------------------------------------
__global__ void zero_kernel(float* __restrict__ out)
{
    const int tid    = blockIdx.x * blockDim.x + threadIdx.x;
    const int stride = gridDim.x * blockDim.x;
    for (int i = tid; i < NCC*SSLICE; i += stride) {
        g_class_h[i] = 0.0f;
        g_class_c[i] = 0.0f;
    }
    for (int i = tid; i < SSLICE; i += stride) {
        g_genh[0][i] = 0.0f;
        g_genc[i]    = 0.0f;
        out[i]       = 0.0f;
    }
}

// ==========================================================================
// General cell: 60 in-ch = 5 chunks of 12 (4 class banks flat view + gen_h),
// 48 gate-ch out. grid (8,16)=(row-tile,batch), block 256 = 64 cols x 4
// row-groups; each thread 2 rows x 48 oc as 24 f32x2 accumulators per row.
// ==========================================================================
#define A_SW   (9*60*48)            // 25920 floats
#define A_SIN  (660*13)             // 8580 floats (10 rows x 66 cols, 13 pad)
#define A_SMEM_BYTES ((A_SW + A_SIN + 48)*4)

__global__ __launch_bounds__(256, 1)
void gen_cell_kernel(const float* __restrict__ Wx, const float* __restrict__ Wh,
                     const float* __restrict__ bias, int par)
{
    extern __shared__ float smem[];
    float* sW  = smem;                 // [9][60][48]
    float* sIn = smem + A_SW;          // [660][13]
    float* sB  = smem + A_SW + A_SIN;  // [48] bias

    const int tid = threadIdx.x;
    const int tx  = tid & 63;
    const int rg  = tid >> 6;
    const int b   = blockIdx.y;
    const int y0  = blockIdx.x * 8;

    const float* genh_in  = g_genh[par];
    float*       genh_out = g_genh[par ^ 1];

    // Stage weights: per tap k, Wx block (48x48) then Wh block (12x48)
    for (int k = 0; k < 9; ++k) {
        const float4* sx = (const float4*)(Wx + k*48*48);
        float4*       dx = (float4*)(sW + (k*60)*48);
        for (int e = tid; e < 576; e += 256) dx[e] = sx[e];
        const float4* sh = (const float4*)(Wh + k*12*48);
        float4*       dh = (float4*)(sW + (k*60 + 48)*48);
        if (tid < 144) dh[tid] = sh[tid];
    }
    if (tid < 12) ((float4*)sB)[tid] = ((const float4*)bias)[tid];

    ull acc[2][24];
    #pragma unroll
    for (int r = 0; r < 2; ++r)
        #pragma unroll
        for (int p = 0; p < 24; ++p) acc[r][p] = 0ull;

    #pragma unroll 1
    for (int ch = 0; ch < 5; ++ch) {
        __syncthreads();
        // Stage 12-ch chunk: 660 px x 3 float4, coalesced LDG.128
        #pragma unroll 1
        for (int e = tid; e < 1980; e += 256) {
            int px = e / 3;
            int q  = e - px*3;
            int yy = px / 66;
            int xx = px - yy*66;
            int gy = y0 + yy - 1;
            int gx = xx - 1;
            float4 v = make_float4(0.f, 0.f, 0.f, 0.f);
            if ((unsigned)gy < 64u && (unsigned)gx < 64u) {
                int pidx = (b*64 + gy)*64 + gx;
                const float* src = (ch < 4)
                    ? g_class_h + (size_t)pidx*48 + ch*12   // raw-reshape view
                    : genh_in   + (size_t)pidx*12;
                v = *(const float4*)(src + q*4);
            }
            float* s = sIn + px*13 + q*4;
            s[0] = v.x; s[1] = v.y; s[2] = v.z; s[3] = v.w;
        }
        __syncthreads();

        #pragma unroll 1
        for (int k = 0; k < 9; ++k) {
            const int ky = k / 3;
            const int kx = k - ky*3;
            const ulonglong2* wb =
                (const ulonglong2*)(sW + (k*60 + ch*12)*48);
            const float* x0 = sIn + ((rg*2 + ky)*66 + tx + kx)*13;
            #pragma unroll 2
            for (int icc = 0; icc < 12; ++icc) {
                ull xp0 = pack2(x0[icc]);
                ull xp1 = pack2(x0[66*13 + icc]);
                const ulonglong2* wp = wb + icc*12;   // 48 floats / channel
                #pragma unroll
                for (int p2 = 0; p2 < 12; ++p2) {
                    ulonglong2 w = wp[p2];
                    ffma2(acc[0][2*p2],   xp0, w.x);
                    ffma2(acc[0][2*p2+1], xp0, w.y);
                    ffma2(acc[1][2*p2],   xp1, w.x);
                    ffma2(acc[1][2*p2+1], xp1, w.y);
                }
            }
        }
    }

    // Local LSTM epilogue, vectorized c/h traffic
    #pragma unroll
    for (int r = 0; r < 2; ++r) {
        float z[48];
        #pragma unroll
        for (int p = 0; p < 24; ++p) {
            float2 v = unpack2(acc[r][p]);
            z[2*p] = v.x; z[2*p+1] = v.y;
        }
        const int gy  = y0 + rg*2 + r;
        const int idx = ((b*64 + gy)*64 + tx)*12;
        float4 c4[3], h4[3];
        #pragma unroll
        for (int q = 0; q < 3; ++q) c4[q] = ((const float4*)(g_genc + idx))[q];
        float* cf = (float*)c4;
        float* hf = (float*)h4;
        #pragma unroll
        for (int j = 0; j < 12; ++j) {
            float zi = z[j]      + sB[j];
            float zf = z[12 + j] + sB[12 + j];
            float zg = z[24 + j] + sB[24 + j];
            float zo = z[36 + j] + sB[36 + j];
            float fi = hsig(zi), ff = hsig(zf), fo = hsig(zo);
            float cn = ff * cf[j] + fi * tanhf(zg);
            cf[j] = cn;
            hf[j] = fo * tanhf(cn);
        }
        #pragma unroll
        for (int q = 0; q < 3; ++q) {
            ((float4*)(g_genc + idx))[q]   = c4[q];
            ((float4*)(genh_out + idx))[q] = h4[q];
        }
    }
}

// ==========================================================================
// Class cell: 36 in-ch = 3 chunks of 12 (frame, fresh gen_h, class_h[cid]).
// Epilogue writes h_new to g_hnew and accumulates the output sum directly.
// ==========================================================================
#define B_SW   (9*36*48)            // 15552 floats
#define B_SIN  (660*13)
#define B_SMEM_BYTES ((B_SW + B_SIN + 48)*4)

__global__ __launch_bounds__(256, 1)
void cls_cell_kernel(const float* __restrict__ x, const int* __restrict__ class_ids,
                     const float* __restrict__ Wx, const float* __restrict__ Wh,
                     const float* __restrict__ bias, int t, int par,
                     float* __restrict__ out)
{
    extern __shared__ float smem[];
    float* sW  = smem;
    float* sIn = smem + B_SW;
    float* sB  = smem + B_SW + B_SIN;

    const int tid = threadIdx.x;
    const int tx  = tid & 63;
    const int rg  = tid >> 6;
    const int b   = blockIdx.y;
    const int y0  = blockIdx.x * 8;
    const int cid = __ldg(class_ids + t);

    const float* genh_new = g_genh[par ^ 1];
    const float* chh      = g_class_h + (size_t)cid * SSLICE;
    const float* frame    = x + (size_t)(b*NTT + t)*4096*12;

    for (int k = 0; k < 9; ++k) {
        const float4* sx = (const float4*)(Wx + k*24*48);
        float4*       dx = (float4*)(sW + (k*36)*48);
        for (int e = tid; e < 288; e += 256) dx[e] = sx[e];
        const float4* sh = (const float4*)(Wh + k*12*48);
        float4*       dh = (float4*)(sW + (k*36 + 24)*48);
        if (tid < 144) dh[tid] = sh[tid];
    }
    if (tid < 12) ((float4*)sB)[tid] = ((const float4*)bias)[tid];

    ull acc[2][24];
    #pragma unroll
    for (int r = 0; r < 2; ++r)
        #pragma unroll
        for (int p = 0; p < 24; ++p) acc[r][p] = 0ull;

    #pragma unroll 1
    for (int ch = 0; ch < 3; ++ch) {
        __syncthreads();
        #pragma unroll 1
        for (int e = tid; e < 1980; e += 256) {
            int px = e / 3;
            int q  = e - px*3;
            int yy = px / 66;
            int xx = px - yy*66;
            int gy = y0 + yy - 1;
            int gx = xx - 1;
            float4 v = make_float4(0.f, 0.f, 0.f, 0.f);
            if ((unsigned)gy < 64u && (unsigned)gx < 64u) {
                int lpix = gy*64 + gx;
                int pidx = b*4096 + lpix;
                const float* src = (ch == 0) ? frame + (size_t)lpix*12
                                 : (ch == 1) ? genh_new + (size_t)pidx*12
                                             : chh + (size_t)pidx*12;
                v = *(const float4*)(src + q*4);
            }
            float* s = sIn + px*13 + q*4;
            s[0] = v.x; s[1] = v.y; s[2] = v.z; s[3] = v.w;
        }
        __syncthreads();

        #pragma unroll 1
        for (int k = 0; k < 9; ++k) {
            const int ky = k / 3;
            const int kx = k - ky*3;
            const ulonglong2* wb =
                (const ulonglong2*)(sW + (k*36 + ch*12)*48);
            const float* x0 = sIn + ((rg*2 + ky)*66 + tx + kx)*13;
            #pragma unroll 2
            for (int icc = 0; icc < 12; ++icc) {
                ull xp0 = pack2(x0[icc]);
                ull xp1 = pack2(x0[66*13 + icc]);
                const ulonglong2* wp = wb + icc*12;   // 48 floats / channel
                #pragma unroll
                for (int p2 = 0; p2 < 12; ++p2) {
                    ulonglong2 w = wp[p2];
                    ffma2(acc[0][2*p2],   xp0, w.x);
                    ffma2(acc[0][2*p2+1], xp0, w.y);
                    ffma2(acc[1][2*p2],   xp1, w.x);
                    ffma2(acc[1][2*p2+1], xp1, w.y);
                }
            }
        }
    }

    float* chc = g_class_c + (size_t)cid * SSLICE;

    #pragma unroll
    for (int r = 0; r < 2; ++r) {
        float z[48];
        #pragma unroll
        for (int p = 0; p < 24; ++p) {
            float2 v = unpack2(acc[r][p]);
            z[2*p] = v.x; z[2*p+1] = v.y;
        }
        const int gy  = y0 + rg*2 + r;
        const int idx = ((b*64 + gy)*64 + tx)*12;
        float4 c4[3], h4[3], o4[3];
        #pragma unroll
        for (int q = 0; q < 3; ++q) {
            c4[q] = ((const float4*)(chc + idx))[q];
            o4[q] = ((const float4*)(out + idx))[q];
        }
        float* cf = (float*)c4;
        float* hf = (float*)h4;
        float* of = (float*)o4;
        #pragma unroll
        for (int j = 0; j < 12; ++j) {
            float zi = z[j]      + sB[j];
            float zf = z[12 + j] + sB[12 + j];
            float zg = z[24 + j] + sB[24 + j];
            float zo = z[36 + j] + sB[36 + j];
            float fi = hsig(zi), ff = hsig(zf), fo = hsig(zo);
            float cn = ff * cf[j] + fi * tanhf(zg);
            float hn = fo * tanhf(cn);
            cf[j] = cn;
            hf[j] = hn;
            of[j] += hn;
        }
        #pragma unroll
        for (int q = 0; q < 3; ++q) {
            ((float4*)(chc + idx))[q]    = c4[q];
            ((float4*)(g_hnew + idx))[q] = h4[q];
            ((float4*)(out + idx))[q]    = o4[q];
        }
    }
}

// --------------------------------------------------------------------------
// Copy-only scatter: h_new -> class_h[cid] (out already accumulated in cls).
// --------------------------------------------------------------------------
__global__ void scatter_kernel(const int* __restrict__ class_ids, int t)
{
    const int cid = __ldg(class_ids + t);
    const int i = blockIdx.x * blockDim.x + threadIdx.x;
    if (i < SSLICE/4) {
        reinterpret_cast<float4*>(g_class_h + (size_t)cid*SSLICE)[i] =
            reinterpret_cast<const float4*>(g_hnew)[i];
    }
}

// --------------------------------------------------------------------------
extern "C" void kernel_launch(void* const* d_in, const int* in_sizes, int n_in,
                              void* d_out, int out_size)
{
    const float* x    = (const float*)d_in[0];
    const int*   cids = (const int*)d_in[1];
    const float* Wxg  = (const float*)d_in[2];
    const float* Whg  = (const float*)d_in[3];
    const float* bg   = (const float*)d_in[4];
    const float* Wxc  = (const float*)d_in[5];
    const float* Whc  = (const float*)d_in[6];
    const float* bc   = (const float*)d_in[7];
    float* out = (float*)d_out;

    cudaFuncSetAttribute(gen_cell_kernel, cudaFuncAttributeMaxDynamicSharedMemorySize, A_SMEM_BYTES);
    cudaFuncSetAttribute(cls_cell_kernel, cudaFuncAttributeMaxDynamicSharedMemorySize, B_SMEM_BYTES);

    zero_kernel<<<1024, 256>>>(out);

    for (int t = 0; t < NTT; ++t) {
        const int par = t & 1;
        gen_cell_kernel<<<dim3(8, 16), 256, A_SMEM_BYTES>>>(Wxg, Whg, bg, par);
        cls_cell_kernel<<<dim3(8, 16), 256, B_SMEM_BYTES>>>(x, cids, Wxc, Whc, bc, t, par, out);
        scatter_kernel<<<(SSLICE/4 + 255)/256, 256>>>(cids, t);
    }
}